// round 1
// baseline (speedup 1.0000x reference)
#include <cuda_runtime.h>
#include <cuda_bf16.h>
#include <mma.h>

using namespace nvcuda;
typedef __nv_bfloat16 bf16;

#define DEVFN __device__ __forceinline__

// ---------------- problem dims ----------------
#define Bv   4
#define Nv   1024
#define Cv   1024
#define Hv   16
#define Dv   64
#define HIDv 4096
#define Tv   (Bv*Nv)     // 4096 tokens
#define BH   (Bv*Hv)     // 64 attention batches

// ---------------- quantizers (exact jnp.round = rintf, clip) ----------------
DEVFN float qz4(float x){ float r = rintf(x*16.0f);  r = fminf(fmaxf(r,-128.0f),127.0f); return r*0.0625f; }
DEVFN float qz7(float x){ float r = rintf(x*128.0f); r = fminf(fmaxf(r,-128.0f),127.0f); return r*0.0078125f; }

// ---------------- device scratch (static, allocation-free) ----------------
__device__ bf16 g_wq  [Cv*Cv];
__device__ bf16 g_wkv [2*Cv*Cv];
__device__ bf16 g_wpr [Cv*Cv];
__device__ bf16 g_wf1 [HIDv*Cv];
__device__ bf16 g_wf2 [Cv*HIDv];
__device__ bf16 g_h1  [Tv*Cv];
__device__ bf16 g_qb  [BH*Nv*Dv];
__device__ bf16 g_kb  [BH*Nv*Dv];
__device__ bf16 g_vb  [BH*Nv*Dv];
__device__ bf16 g_attn[(size_t)BH*Nv*Nv];   // quantized logits (exact in bf16)
__device__ bf16 g_prob[(size_t)BH*Nv*Nv];   // quantized probs  (exact in bf16)
__device__ bf16 g_z2  [Tv*Cv];
__device__ float g_x1 [Tv*Cv];
__device__ bf16 g_h2  [Tv*Cv];
__device__ bf16 g_m   [Tv*HIDv];

// ---------------- elementwise kernels ----------------
__global__ void quantw_k(const float* __restrict__ src, bf16* __restrict__ dst, int n){
    int i = blockIdx.x*blockDim.x + threadIdx.x;
    if(i<n) dst[i] = __float2bfloat16(qz7(src[i]));
}

// h1 = qz4( qz4( qz4(x)*qz4(aw) ) + qz4(ab) )
__global__ void affine1_k(const float* __restrict__ x, const float* __restrict__ aw,
                          const float* __restrict__ ab, bf16* __restrict__ out, int n){
    int i = blockIdx.x*blockDim.x + threadIdx.x;
    if(i<n){
        float a = qz4(aw[0]), b = qz4(ab[0]);
        float t = qz4(x[i]) * a;
        float h = qz4(t) + b;
        out[i] = __float2bfloat16(qz4(h));
    }
}

// row softmax over 1024 quantized logits, then qz(·,8,7)
__global__ void softmax_k(const bf16* __restrict__ s, bf16* __restrict__ p){
    long row = blockIdx.x;                       // BH*Nv rows
    const bf16* sr = s + row*(long)Nv;
    bf16*       pr = p + row*(long)Nv;
    int tid = threadIdx.x;                       // 256 threads
    float v[4];
    float mx = -3.4e38f;
    #pragma unroll
    for(int j=0;j<4;j++){ v[j] = __bfloat162float(sr[tid + j*256]); mx = fmaxf(mx, v[j]); }
    __shared__ float sm[8], ss[8];
    #pragma unroll
    for(int o=16;o;o>>=1) mx = fmaxf(mx, __shfl_xor_sync(0xffffffffu, mx, o));
    if((tid&31)==0) sm[tid>>5] = mx;
    __syncthreads();
    mx = sm[0];
    #pragma unroll
    for(int w=1;w<8;w++) mx = fmaxf(mx, sm[w]);
    float sum = 0.f;
    #pragma unroll
    for(int j=0;j<4;j++){ v[j] = expf(v[j]-mx); sum += v[j]; }
    #pragma unroll
    for(int o=16;o;o>>=1) sum += __shfl_xor_sync(0xffffffffu, sum, o);
    if((tid&31)==0) ss[tid>>5] = sum;
    __syncthreads();
    sum = 0.f;
    #pragma unroll
    for(int w=0;w<8;w++) sum += ss[w];
    #pragma unroll
    for(int j=0;j<4;j++) pr[tid + j*256] = __float2bfloat16(qz7(v[j]/sum));
}

// ---------------- epilogue functors ----------------
struct EpiQ {                       // q -> [B,H,N,D], qz4
    bf16* q;
    DEVFN void operator()(int, int row, int col, float v) const {
        int b=row>>10, n=row&1023, h=col>>6, d=col&63;
        q[(((long)(b*Hv+h))*Nv + n)*Dv + d] = __float2bfloat16(qz4(v));
    }
};
struct EpiKV {                      // kv -> k,v [B,H,N,D], qz4
    bf16* k; bf16* v;
    DEVFN void operator()(int, int row, int col, float acc) const {
        int b=row>>10, n=row&1023;
        int two=col>>10, rem=col&1023, h=rem>>6, d=rem&63;
        bf16 val = __float2bfloat16(qz4(acc));
        long idx = (((long)(b*Hv+h))*Nv + n)*Dv + d;
        if(two==0) k[idx]=val; else v[idx]=val;
    }
};
struct EpiQK {                      // s = qz4(acc*scale)
    bf16* s;
    DEVFN void operator()(int bz, int row, int col, float acc) const {
        s[((long)bz*Nv + row)*(long)Nv + col] = __float2bfloat16(qz4(acc*0.125f));
    }
};
struct EpiPV {                      // z -> [B,N,H*D], qz4
    bf16* z2;
    DEVFN void operator()(int bz, int row, int col, float acc) const {
        int b=bz>>4, h=bz&15;
        z2[((long)(b*Nv+row))*Cv + h*Dv + col] = __float2bfloat16(qz4(acc));
    }
};
struct EpiProj {                    // add1 + affine2, emits x1 (f32) and h2 (bf16, qz4)
    const float* x; const float* pb; const float* aw2; const float* ab2;
    float* x1; bf16* h2;
    DEVFN void operator()(int, int row, int col, float acc) const {
        float y  = acc + qz7(pb[col]);
        float xv = qz4(x[(long)row*Cv+col]) + qz4(y);
        x1[(long)row*Cv+col] = xv;
        float a = qz4(aw2[0]), b = qz4(ab2[0]);
        float t = qz4(xv)*a;
        float h = qz4(t)+b;
        h2[(long)row*Cv+col] = __float2bfloat16(qz4(h));
    }
};
struct EpiFc1 {                     // bias + relu + qz4
    const float* b1; bf16* m;
    DEVFN void operator()(int, int row, int col, float acc) const {
        float y = acc + qz7(b1[col]);
        y = fmaxf(y, 0.f);
        m[(long)row*HIDv+col] = __float2bfloat16(qz4(y));
    }
};
struct EpiFc2 {                     // bias + add2 -> final out f32
    const float* b2; const float* x1; float* out;
    DEVFN void operator()(int, int row, int col, float acc) const {
        float y = acc + qz7(b2[col]);
        out[(long)row*Cv+col] = qz4(x1[(long)row*Cv+col]) + qz4(y);
    }
};

// ---------------- generic wmma GEMM: C = A @ op(B) ----------------
// BT=true : B is [N,K] row-major (compute A @ B^T)   — all qlinear / QK^T
// BT=false: B is [K,N] row-major (compute A @ B)     — PV
constexpr int BM=128, BN=128, BK=32, BKP=40;   // BKP*2B = 80B, multiple of 16 ✓

template<bool BT, class Epi>
__global__ void __launch_bounds__(256)
gemm_k(const bf16* __restrict__ A, const bf16* __restrict__ B,
       int M, int Nn, int K, long asb, long bsb, Epi epi)
{
    __shared__ bf16 As[BM][BKP];
    __shared__ bf16 Bs[BN][BKP];
    __shared__ float stage[8][16][20];    // ld=20 f32 = 80B, multiple of 16 ✓

    int tid  = threadIdx.x;
    int warp = tid>>5, lane = tid&31;
    int m0 = blockIdx.y*BM, n0 = blockIdx.x*BN;
    int bz = blockIdx.z;
    A += (long)bz*asb;  B += (long)bz*bsb;

    wmma::fragment<wmma::accumulator,16,16,16,float> acc[2][4];
    #pragma unroll
    for(int im=0;im<2;im++)
        #pragma unroll
        for(int in=0;in<4;in++) wmma::fill_fragment(acc[im][in], 0.0f);

    int wm = warp & 3;        // 4 row-blocks of 32
    int wn = warp >> 2;       // 2 col-blocks of 64

    for(int k0=0;k0<K;k0+=BK){
        // A tile: vectorized 4x bf16 (8B) loads
        #pragma unroll
        for(int i=tid;i<BM*BK/4;i+=256){
            int r=i>>3, c=(i&7)*4;
            *reinterpret_cast<uint2*>(&As[r][c]) =
                *reinterpret_cast<const uint2*>(A + (long)(m0+r)*K + k0 + c);
        }
        if (BT){
            #pragma unroll
            for(int i=tid;i<BN*BK/4;i+=256){
                int r=i>>3, c=(i&7)*4;
                uint2 v = make_uint2(0u,0u);
                if(n0+r<Nn) v = *reinterpret_cast<const uint2*>(B + (long)(n0+r)*K + k0 + c);
                *reinterpret_cast<uint2*>(&Bs[r][c]) = v;
            }
        } else {
            for(int i=tid;i<BN*BK;i+=256){
                int n=i&(BN-1), k=i>>7;
                bf16 v = __float2bfloat16(0.f);
                if(n0+n<Nn) v = B[(long)(k0+k)*Nn + n0+n];
                Bs[n][k]=v;
            }
        }
        __syncthreads();
        #pragma unroll
        for(int kk=0;kk<BK;kk+=16){
            wmma::fragment<wmma::matrix_a,16,16,16,bf16,wmma::row_major> af[2];
            wmma::fragment<wmma::matrix_b,16,16,16,bf16,wmma::col_major> bfm[4];
            #pragma unroll
            for(int im=0;im<2;im++) wmma::load_matrix_sync(af[im],  &As[wm*32+im*16][kk], BKP);
            #pragma unroll
            for(int in=0;in<4;in++) wmma::load_matrix_sync(bfm[in], &Bs[wn*64+in*16][kk], BKP);
            #pragma unroll
            for(int im=0;im<2;im++)
                #pragma unroll
                for(int in=0;in<4;in++)
                    wmma::mma_sync(acc[im][in], af[im], bfm[in], acc[im][in]);
        }
        __syncthreads();
    }

    // epilogue via per-warp smem staging
    #pragma unroll
    for(int im=0;im<2;im++){
        #pragma unroll
        for(int in=0;in<4;in++){
            int r0 = m0 + wm*32 + im*16;
            int c0 = n0 + wn*64 + in*16;
            if (c0 >= Nn) continue;        // N dims are multiples of 16
            wmma::store_matrix_sync(&stage[warp][0][0], acc[im][in], 20, wmma::mem_row_major);
            __syncwarp();
            #pragma unroll
            for(int j=lane;j<256;j+=32){
                int rr=j>>4, cc=j&15;
                epi(bz, r0+rr, c0+cc, stage[warp][rr][cc]);
            }
            __syncwarp();
        }
    }
}

// ---------------- host launcher ----------------
static inline dim3 gdim(int M,int Nn,int bat){ return dim3((Nn+BN-1)/BN,(M+BM-1)/BM,bat); }

extern "C" void kernel_launch(void* const* d_in, const int* in_sizes, int n_in,
                              void* d_out, int out_size)
{
    (void)in_sizes; (void)n_in; (void)out_size;
    const float* x   = (const float*)d_in[0];
    const float* qw  = (const float*)d_in[1];
    const float* kvw = (const float*)d_in[2];
    const float* pw  = (const float*)d_in[3];
    const float* pb  = (const float*)d_in[4];
    const float* f1w = (const float*)d_in[5];
    const float* f1b = (const float*)d_in[6];
    const float* f2w = (const float*)d_in[7];
    const float* f2b = (const float*)d_in[8];
    const float* a1w = (const float*)d_in[9];
    const float* a1b = (const float*)d_in[10];
    const float* a2w = (const float*)d_in[11];
    const float* a2b = (const float*)d_in[12];
    float* out = (float*)d_out;

    bf16 *wq,*wkv,*wpr,*wf1,*wf2,*h1,*qb,*kb,*vb,*attn,*prob,*z2,*h2,*m;
    float *x1;
    cudaGetSymbolAddress((void**)&wq,  g_wq);
    cudaGetSymbolAddress((void**)&wkv, g_wkv);
    cudaGetSymbolAddress((void**)&wpr, g_wpr);
    cudaGetSymbolAddress((void**)&wf1, g_wf1);
    cudaGetSymbolAddress((void**)&wf2, g_wf2);
    cudaGetSymbolAddress((void**)&h1,  g_h1);
    cudaGetSymbolAddress((void**)&qb,  g_qb);
    cudaGetSymbolAddress((void**)&kb,  g_kb);
    cudaGetSymbolAddress((void**)&vb,  g_vb);
    cudaGetSymbolAddress((void**)&attn,g_attn);
    cudaGetSymbolAddress((void**)&prob,g_prob);
    cudaGetSymbolAddress((void**)&z2,  g_z2);
    cudaGetSymbolAddress((void**)&x1,  g_x1);
    cudaGetSymbolAddress((void**)&h2,  g_h2);
    cudaGetSymbolAddress((void**)&m,   g_m);

    // 1) quantize weights (qz 8,7 -> bf16, exact)
    quantw_k<<<(Cv*Cv+255)/256,       256>>>(qw,  wq,  Cv*Cv);
    quantw_k<<<(2*Cv*Cv+255)/256,     256>>>(kvw, wkv, 2*Cv*Cv);
    quantw_k<<<(Cv*Cv+255)/256,       256>>>(pw,  wpr, Cv*Cv);
    quantw_k<<<(HIDv*Cv+255)/256,     256>>>(f1w, wf1, HIDv*Cv);
    quantw_k<<<(Cv*HIDv+255)/256,     256>>>(f2w, wf2, Cv*HIDv);

    // 2) affine1 + input quant -> h1
    affine1_k<<<(Tv*Cv+255)/256, 256>>>(x, a1w, a1b, h1, Tv*Cv);

    // 3) q / kv projections
    { EpiQ  e{qb};       gemm_k<true ><<<gdim(Tv,Cv,1),   256>>>(h1, wq,  Tv, Cv,   Cv, 0,0, e); }
    { EpiKV e{kb,vb};    gemm_k<true ><<<gdim(Tv,2*Cv,1), 256>>>(h1, wkv, Tv, 2*Cv, Cv, 0,0, e); }

    // 4) attention logits: per-(b,h) Q @ K^T, qz4(·*scale)
    { EpiQK e{attn};     gemm_k<true ><<<gdim(Nv,Nv,BH),  256>>>(qb, kb, Nv, Nv, Dv,
                                                                 (long)Nv*Dv, (long)Nv*Dv, e); }
    // 5) softmax + qz7
    softmax_k<<<BH*Nv, 256>>>(attn, prob);

    // 6) P @ V -> z2 [B,N,C], qz4
    { EpiPV e{z2};       gemm_k<false><<<gdim(Nv,Dv,BH),  256>>>(prob, vb, Nv, Dv, Nv,
                                                                 (long)Nv*Nv, (long)Nv*Dv, e); }
    // 7) proj + add1 + affine2 -> x1 (f32), h2 (bf16)
    { EpiProj e{x, pb, a2w, a2b, x1, h2};
                         gemm_k<true ><<<gdim(Tv,Cv,1),   256>>>(z2, wpr, Tv, Cv, Cv, 0,0, e); }
    // 8) fc1 + relu + qz4 -> m
    { EpiFc1 e{f1b, m};  gemm_k<true ><<<gdim(Tv,HIDv,1), 256>>>(h2, wf1, Tv, HIDv, Cv, 0,0, e); }
    // 9) fc2 + add2 -> out
    { EpiFc2 e{f2b, x1, out};
                         gemm_k<true ><<<gdim(Tv,Cv,1),   256>>>(m,  wf2, Tv, Cv, HIDv, 0,0, e); }
}

// round 4
// speedup vs baseline: 1.5443x; 1.5443x over previous
#include <cuda_runtime.h>
#include <cuda_bf16.h>
#include <cstdint>

typedef __nv_bfloat16 bf16;
#define DEVFN __device__ __forceinline__

// NOTE: toolchain targets sm_103 (no 'a') -> tcgen05/TMEM unavailable.
// Ceiling is mma.sync (HMMA) + cp.async; this file uses only sm_80-baseline ISA.

// ---------------- problem dims ----------------
#define Bv   4
#define Nv   1024
#define Cv   1024
#define Hv   16
#define Dv   64
#define HIDv 4096
#define Tv   (Bv*Nv)     // 4096 tokens
#define BH   (Bv*Hv)     // 64 attention batches

// ---------------- quantizers (exact jnp.round = rintf, clip) ----------------
DEVFN float qz4(float x){ float r = rintf(x*16.0f);  r = fminf(fmaxf(r,-128.0f),127.0f); return r*0.0625f; }
DEVFN float qz7(float x){ float r = rintf(x*128.0f); r = fminf(fmaxf(r,-128.0f),127.0f); return r*0.0078125f; }

// ---------------- device scratch ----------------
__device__ __align__(128) bf16 g_wq  [Cv*Cv];
__device__ __align__(128) bf16 g_wkv [2*Cv*Cv];
__device__ __align__(128) bf16 g_wpr [Cv*Cv];
__device__ __align__(128) bf16 g_wf1 [HIDv*Cv];
__device__ __align__(128) bf16 g_wf2 [Cv*HIDv];
__device__ __align__(128) bf16 g_h1  [Tv*Cv];
__device__ __align__(128) bf16 g_qb  [BH*Nv*Dv];
__device__ __align__(128) bf16 g_kb  [BH*Nv*Dv];
__device__ __align__(128) bf16 g_vb  [BH*Nv*Dv];     // [bh, n, d] row-major
__device__ __align__(128) bf16 g_attn[(size_t)BH*Nv*Nv];
__device__ __align__(128) bf16 g_prob[(size_t)BH*Nv*Nv];
__device__ __align__(128) bf16 g_z2  [Tv*Cv];
__device__ __align__(128) float g_x1 [Tv*Cv];
__device__ __align__(128) bf16 g_h2  [Tv*Cv];
__device__ __align__(128) bf16 g_m   [Tv*HIDv];

// ---------------- PTX helpers (sm_80 baseline only) ----------------
DEVFN uint32_t s2u(const void* p){
    uint32_t a;
    asm("{ .reg .u64 t; cvta.to.shared.u64 t, %1; cvt.u32.u64 %0, t; }" : "=r"(a) : "l"(p));
    return a;
}
DEVFN void cpasync16(uint32_t d, const void* s){
    asm volatile("cp.async.cg.shared.global [%0], [%1], 16;" :: "r"(d), "l"(s));
}
DEVFN void cpcommit(){ asm volatile("cp.async.commit_group;" ::: "memory"); }
template<int N> DEVFN void cpwait(){ asm volatile("cp.async.wait_group %0;" :: "n"(N) : "memory"); }

DEVFN void ldsm4(uint32_t* r, uint32_t addr){
    asm volatile("ldmatrix.sync.aligned.m8n8.x4.shared.b16 {%0,%1,%2,%3}, [%4];"
        : "=r"(r[0]), "=r"(r[1]), "=r"(r[2]), "=r"(r[3]) : "r"(addr));
}
DEVFN void ldsm4t(uint32_t* r, uint32_t addr){
    asm volatile("ldmatrix.sync.aligned.m8n8.x4.trans.shared.b16 {%0,%1,%2,%3}, [%4];"
        : "=r"(r[0]), "=r"(r[1]), "=r"(r[2]), "=r"(r[3]) : "r"(addr));
}
DEVFN void mma16816(float* c, const uint32_t* a, const uint32_t* b){
    asm volatile("mma.sync.aligned.m16n8k16.row.col.f32.bf16.bf16.f32 "
        "{%0,%1,%2,%3}, {%4,%5,%6,%7}, {%8,%9}, {%0,%1,%2,%3};"
        : "+f"(c[0]), "+f"(c[1]), "+f"(c[2]), "+f"(c[3])
        : "r"(a[0]), "r"(a[1]), "r"(a[2]), "r"(a[3]), "r"(b[0]), "r"(b[1]));
}

DEVFN void st_bf2(bf16* p, float a, float b){
    __nv_bfloat162 t = __halves2bfloat162(__float2bfloat16(a), __float2bfloat16(b));
    *reinterpret_cast<__nv_bfloat162*>(p) = t;
}

// ---------------- epilogue functors (2-column granularity, col even) ----------------
struct EpiQ {
    bf16* q;
    DEVFN void operator()(int, int row, int col, float v0, float v1) const {
        int b=row>>10, n=row&1023, h=col>>6, d=col&63;
        st_bf2(q + (((long)(b*Hv+h))*Nv + n)*Dv + d, qz4(v0), qz4(v1));
    }
};
struct EpiKV {
    bf16* k; bf16* vv;
    DEVFN void operator()(int, int row, int col, float v0, float v1) const {
        int b=row>>10, n=row&1023;
        int rem=col&1023, h=rem>>6, d=rem&63;
        bf16* dst = ((col>>10)==0 ? k : vv) + (((long)(b*Hv+h))*Nv + n)*Dv + d;
        st_bf2(dst, qz4(v0), qz4(v1));
    }
};
struct EpiQK {
    bf16* s;
    DEVFN void operator()(int bz, int row, int col, float v0, float v1) const {
        st_bf2(s + ((long)bz*Nv + row)*(long)Nv + col, qz4(v0*0.125f), qz4(v1*0.125f));
    }
};
struct EpiPV {
    bf16* z2;
    DEVFN void operator()(int bz, int row, int col, float v0, float v1) const {
        int b=bz>>4, h=bz&15;
        st_bf2(z2 + ((long)(b*Nv+row))*Cv + h*Dv + col, qz4(v0), qz4(v1));
    }
};
struct EpiProj {
    const float* x; const float* pb; const float* aw2; const float* ab2;
    float* x1; bf16* h2;
    DEVFN void operator()(int, int row, int col, float v0, float v1) const {
        float a = qz4(aw2[0]), bb = qz4(ab2[0]);
        float2 xv = *(const float2*)(x + (long)row*Cv + col);
        float2 pv = *(const float2*)(pb + col);
        float y0 = v0 + qz7(pv.x),  y1 = v1 + qz7(pv.y);
        float o0 = qz4(xv.x) + qz4(y0), o1 = qz4(xv.y) + qz4(y1);
        *(float2*)(x1 + (long)row*Cv + col) = make_float2(o0, o1);
        float h0 = qz4(qz4(qz4(o0)*a) + bb);
        float h1 = qz4(qz4(qz4(o1)*a) + bb);
        st_bf2(h2 + (long)row*Cv + col, h0, h1);
    }
};
struct EpiFc1 {
    const float* b1; bf16* m;
    DEVFN void operator()(int, int row, int col, float v0, float v1) const {
        float2 bv = *(const float2*)(b1 + col);
        float y0 = fmaxf(v0 + qz7(bv.x), 0.f);
        float y1 = fmaxf(v1 + qz7(bv.y), 0.f);
        st_bf2(m + (long)row*HIDv + col, qz4(y0), qz4(y1));
    }
};
struct EpiFc2 {
    const float* b2; const float* x1; float* out;
    DEVFN void operator()(int, int row, int col, float v0, float v1) const {
        float2 bv = *(const float2*)(b2 + col);
        float2 xv = *(const float2*)(x1 + (long)row*Cv + col);
        float y0 = v0 + qz7(bv.x), y1 = v1 + qz7(bv.y);
        *(float2*)(out + (long)row*Cv + col) =
            make_float2(qz4(xv.x) + qz4(y0), qz4(xv.y) + qz4(y1));
    }
};

// ---------------- pipelined mma.sync GEMM ----------------
// C[128 x TN-block] = A @ op(B).  BT=true: B[Nn,K] K-major (A@B^T, ldmatrix non-trans)
//                                 BT=false: B[K,Nn] N-major (A@B, ldmatrix.trans)
// BM=128, BK=32, 256 threads = 8 warps (4 along M x 2 along N), 3-stage cp.async.
template<int TN, bool BT, class Epi>
__global__ void __launch_bounds__(256,2)
gemm_mma(const bf16* __restrict__ A, const bf16* __restrict__ Bm,
         int M, int Nn, int K, long asb, long bsb, Epi epi)
{
    constexpr int S = 3;
    constexpr int AROW = 80;                 // bytes per padded A row (32 bf16 + pad)
    constexpr int ASZ  = 128*AROW;           // 10240 B
    constexpr int BROWT = (TN+8)*2;          // trans-layout row bytes
    constexpr int BSZ  = BT ? TN*AROW : 32*BROWT;
    constexpr int STG  = ASZ + BSZ;
    constexpr int WN   = TN/2;               // warp n extent
    constexpr int NB8  = TN/16;              // n8 frags per warp

    extern __shared__ char dsm[];
    uint32_t base = s2u(dsm);

    int tid = threadIdx.x, wid = tid>>5, lane = tid&31;
    int wm = wid & 3, wn = wid >> 2;
    int m0 = blockIdx.y*128, n0 = blockIdx.x*TN, bz = blockIdx.z;
    const bf16* Ab = A + (long)bz*asb + (long)m0*K;
    const bf16* Bb = BT ? (Bm + (long)bz*bsb + (long)n0*K)
                        : (Bm + (long)bz*bsb + n0);

    const int KC = K >> 5;                   // BK=32 chunks

    auto load = [&](int ch, int st){
        uint32_t ab = base + st*STG;
        uint32_t bb = ab + ASZ;
        // A tile: 128 rows x 32 cols -> 512 x 16B chunks
        #pragma unroll
        for(int j=0;j<2;j++){
            int i = tid + j*256;
            int r = i>>2, c = i&3;
            cpasync16(ab + r*AROW + c*16, Ab + (long)r*K + ch*32 + c*8);
        }
        if (BT){
            #pragma unroll
            for(int j=0;j<TN/64;j++){
                int i = tid + j*256;
                int r = i>>2, c = i&3;
                cpasync16(bb + r*AROW + c*16, Bb + (long)r*K + ch*32 + c*8);
            }
        } else {
            // 32 rows x TN cols
            #pragma unroll
            for(int j=0;j<(32*TN/8+255)/256;j++){
                int i = tid + j*256;
                if (32*TN/8 > 256 || i < 32*TN/8){
                    int r = i/(TN/8), c = i%(TN/8);
                    cpasync16(bb + r*BROWT + c*16, Bb + (long)(ch*32+r)*Nn + c*8);
                }
            }
        }
        cpcommit();
    };

    float acc[2][NB8][4];
    #pragma unroll
    for(int im=0;im<2;im++)
        #pragma unroll
        for(int j=0;j<NB8;j++)
            #pragma unroll
            for(int u=0;u<4;u++) acc[im][j][u]=0.f;

    int nPre = (KC < S-1) ? KC : S-1;
    for(int c=0;c<nPre;c++) load(c, c % S);

    int t  = lane>>3, lr = lane&7;
    int rAdd = (t&1)*8 + lr;                 // ldmatrix lane row offset
    int cAdd = (t>>1)*8;                     // ldmatrix lane col offset (elements)

    for(int c=0;c<KC;c++){
        if (c < KC-1) cpwait<1>(); else cpwait<0>();
        __syncthreads();
        int nxt = c + S - 1;
        if (nxt < KC) load(nxt, nxt % S);

        uint32_t ab = base + (c%S)*STG;
        uint32_t bb = ab + ASZ;
        #pragma unroll
        for(int kk=0; kk<32; kk+=16){
            uint32_t afr[2][4];
            #pragma unroll
            for(int im=0;im<2;im++){
                int row = wm*32 + im*16 + rAdd;
                ldsm4(afr[im], ab + row*AROW + (kk + cAdd)*2);
            }
            uint32_t bfr[NB8][2];
            #pragma unroll
            for(int g=0; g<TN/32; g++){
                uint32_t r4[4];
                if (BT){
                    int row = wn*WN + g*16 + rAdd;
                    ldsm4(r4, bb + row*AROW + (kk + cAdd)*2);
                    bfr[2*g][0]=r4[0]; bfr[2*g][1]=r4[2];
                    bfr[2*g+1][0]=r4[1]; bfr[2*g+1][1]=r4[3];
                } else {
                    int rowk = kk + rAdd;
                    int coln = wn*WN + g*16 + cAdd;
                    ldsm4t(r4, bb + rowk*BROWT + coln*2);
                    bfr[2*g][0]=r4[0]; bfr[2*g][1]=r4[1];
                    bfr[2*g+1][0]=r4[2]; bfr[2*g+1][1]=r4[3];
                }
            }
            #pragma unroll
            for(int im=0;im<2;im++)
                #pragma unroll
                for(int j=0;j<NB8;j++)
                    mma16816(acc[im][j], afr[im], bfr[j]);
        }
    }

    // register-direct epilogue
    int row0 = m0 + wm*32 + (lane>>2);
    int col0 = n0 + wn*WN + (lane&3)*2;
    #pragma unroll
    for(int im=0;im<2;im++){
        #pragma unroll
        for(int j=0;j<NB8;j++){
            int r = row0 + im*16;
            int cc = col0 + j*8;
            epi(bz, r,   cc, acc[im][j][0], acc[im][j][1]);
            epi(bz, r+8, cc, acc[im][j][2], acc[im][j][3]);
        }
    }
}

// ---------------- elementwise kernels ----------------
__global__ void quantw4_k(const float4* __restrict__ src, uint2* __restrict__ dst, int n4){
    int i = blockIdx.x*blockDim.x + threadIdx.x;
    if(i<n4){
        float4 v = src[i];
        __nv_bfloat162 lo = __halves2bfloat162(__float2bfloat16(qz7(v.x)), __float2bfloat16(qz7(v.y)));
        __nv_bfloat162 hi = __halves2bfloat162(__float2bfloat16(qz7(v.z)), __float2bfloat16(qz7(v.w)));
        dst[i] = make_uint2(*(uint32_t*)&lo, *(uint32_t*)&hi);
    }
}
__global__ void affine4_k(const float4* __restrict__ x, const float* __restrict__ aw,
                          const float* __restrict__ ab, uint2* __restrict__ out, int n4){
    int i = blockIdx.x*blockDim.x + threadIdx.x;
    if(i<n4){
        float a = qz4(aw[0]), b = qz4(ab[0]);
        float4 v = x[i];
        float o[4] = {v.x,v.y,v.z,v.w};
        #pragma unroll
        for(int u=0;u<4;u++){ float t = qz4(o[u])*a; o[u] = qz4(qz4(t)+b); }
        __nv_bfloat162 lo = __halves2bfloat162(__float2bfloat16(o[0]), __float2bfloat16(o[1]));
        __nv_bfloat162 hi = __halves2bfloat162(__float2bfloat16(o[2]), __float2bfloat16(o[3]));
        out[i] = make_uint2(*(uint32_t*)&lo, *(uint32_t*)&hi);
    }
}
__global__ void softmax_k(const bf16* __restrict__ s, bf16* __restrict__ p){
    long row = blockIdx.x;
    const bf16* sr = s + row*(long)Nv;
    bf16*       pr = p + row*(long)Nv;
    int tid = threadIdx.x;                       // 256 threads
    float v[4];
    float mx = -3.4e38f;
    #pragma unroll
    for(int j=0;j<4;j++){ v[j] = __bfloat162float(sr[tid + j*256]); mx = fmaxf(mx, v[j]); }
    __shared__ float sm[8], ss[8];
    #pragma unroll
    for(int o=16;o;o>>=1) mx = fmaxf(mx, __shfl_xor_sync(0xffffffffu, mx, o));
    if((tid&31)==0) sm[tid>>5] = mx;
    __syncthreads();
    mx = sm[0];
    #pragma unroll
    for(int w=1;w<8;w++) mx = fmaxf(mx, sm[w]);
    float sum = 0.f;
    #pragma unroll
    for(int j=0;j<4;j++){ v[j] = expf(v[j]-mx); sum += v[j]; }
    #pragma unroll
    for(int o=16;o;o>>=1) sum += __shfl_xor_sync(0xffffffffu, sum, o);
    if((tid&31)==0) ss[tid>>5] = sum;
    __syncthreads();
    sum = 0.f;
    #pragma unroll
    for(int w=0;w<8;w++) sum += ss[w];
    float inv = 1.0f/sum;
    #pragma unroll
    for(int j=0;j<4;j++) pr[tid + j*256] = __float2bfloat16(qz7(v[j]*inv));
}

// ---------------- host launcher ----------------
static inline dim3 gdim(int M,int Nn,int TN,int bat){ return dim3(Nn/TN, M/128, bat); }
#define SMEM_MMA(TN,BT) (3*(128*80 + ((BT) ? (TN)*80 : 32*((TN)+8)*2)))

extern "C" void kernel_launch(void* const* d_in, const int* in_sizes, int n_in,
                              void* d_out, int out_size)
{
    (void)in_sizes; (void)n_in; (void)out_size;
    const float* x   = (const float*)d_in[0];
    const float* qw  = (const float*)d_in[1];
    const float* kvw = (const float*)d_in[2];
    const float* pw  = (const float*)d_in[3];
    const float* pb  = (const float*)d_in[4];
    const float* f1w = (const float*)d_in[5];
    const float* f1b = (const float*)d_in[6];
    const float* f2w = (const float*)d_in[7];
    const float* f2b = (const float*)d_in[8];
    const float* a1w = (const float*)d_in[9];
    const float* a1b = (const float*)d_in[10];
    const float* a2w = (const float*)d_in[11];
    const float* a2b = (const float*)d_in[12];
    float* out = (float*)d_out;

    bf16 *wq,*wkv,*wpr,*wf1,*wf2,*h1,*qb,*kb,*vb,*attn,*prob,*z2,*h2,*m;
    float *x1;
    cudaGetSymbolAddress((void**)&wq,  g_wq);
    cudaGetSymbolAddress((void**)&wkv, g_wkv);
    cudaGetSymbolAddress((void**)&wpr, g_wpr);
    cudaGetSymbolAddress((void**)&wf1, g_wf1);
    cudaGetSymbolAddress((void**)&wf2, g_wf2);
    cudaGetSymbolAddress((void**)&h1,  g_h1);
    cudaGetSymbolAddress((void**)&qb,  g_qb);
    cudaGetSymbolAddress((void**)&kb,  g_kb);
    cudaGetSymbolAddress((void**)&vb,  g_vb);
    cudaGetSymbolAddress((void**)&attn,g_attn);
    cudaGetSymbolAddress((void**)&prob,g_prob);
    cudaGetSymbolAddress((void**)&z2,  g_z2);
    cudaGetSymbolAddress((void**)&x1,  g_x1);
    cudaGetSymbolAddress((void**)&h2,  g_h2);
    cudaGetSymbolAddress((void**)&m,   g_m);

    cudaFuncSetAttribute(gemm_mma<128,true ,EpiQ  >, cudaFuncAttributeMaxDynamicSharedMemorySize, SMEM_MMA(128,true));
    cudaFuncSetAttribute(gemm_mma<128,true ,EpiKV >, cudaFuncAttributeMaxDynamicSharedMemorySize, SMEM_MMA(128,true));
    cudaFuncSetAttribute(gemm_mma<128,true ,EpiQK >, cudaFuncAttributeMaxDynamicSharedMemorySize, SMEM_MMA(128,true));
    cudaFuncSetAttribute(gemm_mma<128,true ,EpiProj>,cudaFuncAttributeMaxDynamicSharedMemorySize, SMEM_MMA(128,true));
    cudaFuncSetAttribute(gemm_mma<128,true ,EpiFc1>, cudaFuncAttributeMaxDynamicSharedMemorySize, SMEM_MMA(128,true));
    cudaFuncSetAttribute(gemm_mma<128,true ,EpiFc2>, cudaFuncAttributeMaxDynamicSharedMemorySize, SMEM_MMA(128,true));
    cudaFuncSetAttribute(gemm_mma< 64,false,EpiPV >, cudaFuncAttributeMaxDynamicSharedMemorySize, SMEM_MMA(64,false));

    // 1) quantize weights (qz 8,7 -> bf16, exact)
    quantw4_k<<<(Cv*Cv/4+255)/256,   256>>>((const float4*)qw,  (uint2*)wq,  Cv*Cv/4);
    quantw4_k<<<(2*Cv*Cv/4+255)/256, 256>>>((const float4*)kvw, (uint2*)wkv, 2*Cv*Cv/4);
    quantw4_k<<<(Cv*Cv/4+255)/256,   256>>>((const float4*)pw,  (uint2*)wpr, Cv*Cv/4);
    quantw4_k<<<(HIDv*Cv/4+255)/256, 256>>>((const float4*)f1w, (uint2*)wf1, HIDv*Cv/4);
    quantw4_k<<<(Cv*HIDv/4+255)/256, 256>>>((const float4*)f2w, (uint2*)wf2, Cv*HIDv/4);

    // 2) affine1 + input quant -> h1
    affine4_k<<<(Tv*Cv/4+255)/256, 256>>>((const float4*)x, a1w, a1b, (uint2*)h1, Tv*Cv/4);

    // 3) q / kv projections
    { EpiQ  e{qb};
      gemm_mma<128,true,EpiQ ><<<gdim(Tv,Cv,128,1),    256, SMEM_MMA(128,true)>>>(h1, wq,  Tv, Cv,   Cv, 0,0, e); }
    { EpiKV e{kb,vb};
      gemm_mma<128,true,EpiKV><<<gdim(Tv,2*Cv,128,1),  256, SMEM_MMA(128,true)>>>(h1, wkv, Tv, 2*Cv, Cv, 0,0, e); }

    // 4) attention logits: per-(b,h) Q @ K^T, qz4(acc * D^-1/2)
    { EpiQK e{attn};
      gemm_mma<128,true,EpiQK><<<gdim(Nv,Nv,128,BH),   256, SMEM_MMA(128,true)>>>(qb, kb, Nv, Nv, Dv,
                                                        (long)Nv*Dv, (long)Nv*Dv, e); }
    // 5) softmax + qz7
    softmax_k<<<BH*Nv, 256>>>(attn, prob);

    // 6) P @ V -> z2 [B,N,C], qz4  (V is [n,d]: B[K,N] layout, ldmatrix.trans path)
    { EpiPV e{z2};
      gemm_mma<64,false,EpiPV><<<gdim(Nv,Dv,64,BH),    256, SMEM_MMA(64,false)>>>(prob, vb, Nv, Dv, Nv,
                                                        (long)Nv*Nv, (long)Nv*Dv, e); }
    // 7) proj + add1 + affine2 -> x1 (f32), h2 (bf16)
    { EpiProj e{x, pb, a2w, a2b, x1, h2};
      gemm_mma<128,true,EpiProj><<<gdim(Tv,Cv,128,1),  256, SMEM_MMA(128,true)>>>(z2, wpr, Tv, Cv, Cv, 0,0, e); }
    // 8) fc1 + relu + qz4 -> m
    { EpiFc1 e{f1b, m};
      gemm_mma<128,true,EpiFc1><<<gdim(Tv,HIDv,128,1), 256, SMEM_MMA(128,true)>>>(h2, wf1, Tv, HIDv, Cv, 0,0, e); }
    // 9) fc2 + add2 -> out
    { EpiFc2 e{f2b, x1, out};
      gemm_mma<128,true,EpiFc2><<<gdim(Tv,Cv,128,1),   256, SMEM_MMA(128,true)>>>(m, wf2, Tv, Cv, HIDv, 0,0, e); }
}

// round 5
// speedup vs baseline: 1.8044x; 1.1684x over previous
#include <cuda_runtime.h>
#include <cuda_bf16.h>
#include <cstdint>

typedef __nv_bfloat16 bf16;
#define DEVFN __device__ __forceinline__

// toolchain targets sm_103 (no 'a') -> tcgen05 unavailable; mma.sync + cp.async path.

// ---------------- problem dims ----------------
#define Bv   4
#define Nv   1024
#define Cv   1024
#define Hv   16
#define Dv   64
#define HIDv 4096
#define Tv   (Bv*Nv)
#define BH   (Bv*Hv)

// ---------------- quantizers ----------------
DEVFN float qz4(float x){ float r = rintf(x*16.0f);  r = fminf(fmaxf(r,-128.0f),127.0f); return r*0.0625f; }
DEVFN float qz7(float x){ float r = rintf(x*128.0f); r = fminf(fmaxf(r,-128.0f),127.0f); return r*0.0078125f; }

// ---------------- device scratch ----------------
__device__ __align__(128) bf16 g_wq  [Cv*Cv];
__device__ __align__(128) bf16 g_wkv [2*Cv*Cv];
__device__ __align__(128) bf16 g_wpr [Cv*Cv];
__device__ __align__(128) bf16 g_wf1 [HIDv*Cv];
__device__ __align__(128) bf16 g_wf2 [Cv*HIDv];
__device__ __align__(128) bf16 g_h1  [Tv*Cv];
__device__ __align__(128) bf16 g_qb  [BH*Nv*Dv];
__device__ __align__(128) bf16 g_kb  [BH*Nv*Dv];
__device__ __align__(128) bf16 g_vb  [BH*Nv*Dv];
__device__ __align__(128) bf16 g_z2  [Tv*Cv];
__device__ __align__(128) float g_x1 [Tv*Cv];
__device__ __align__(128) bf16 g_h2  [Tv*Cv];
__device__ __align__(128) bf16 g_m   [Tv*HIDv];

// ---------------- PTX helpers ----------------
DEVFN uint32_t s2u(const void* p){
    uint32_t a;
    asm("{ .reg .u64 t; cvta.to.shared.u64 t, %1; cvt.u32.u64 %0, t; }" : "=r"(a) : "l"(p));
    return a;
}
DEVFN void cpasync16(uint32_t d, const void* s){
    asm volatile("cp.async.cg.shared.global [%0], [%1], 16;" :: "r"(d), "l"(s));
}
DEVFN void cpcommit(){ asm volatile("cp.async.commit_group;" ::: "memory"); }
template<int N> DEVFN void cpwait(){ asm volatile("cp.async.wait_group %0;" :: "n"(N) : "memory"); }

DEVFN void ldsm4(uint32_t* r, uint32_t addr){
    asm volatile("ldmatrix.sync.aligned.m8n8.x4.shared.b16 {%0,%1,%2,%3}, [%4];"
        : "=r"(r[0]), "=r"(r[1]), "=r"(r[2]), "=r"(r[3]) : "r"(addr));
}
DEVFN void ldsm4t(uint32_t* r, uint32_t addr){
    asm volatile("ldmatrix.sync.aligned.m8n8.x4.trans.shared.b16 {%0,%1,%2,%3}, [%4];"
        : "=r"(r[0]), "=r"(r[1]), "=r"(r[2]), "=r"(r[3]) : "r"(addr));
}
DEVFN void mma16816(float* c, const uint32_t* a, const uint32_t* b){
    asm volatile("mma.sync.aligned.m16n8k16.row.col.f32.bf16.bf16.f32 "
        "{%0,%1,%2,%3}, {%4,%5,%6,%7}, {%8,%9}, {%0,%1,%2,%3};"
        : "+f"(c[0]), "+f"(c[1]), "+f"(c[2]), "+f"(c[3])
        : "r"(a[0]), "r"(a[1]), "r"(a[2]), "r"(a[3]), "r"(b[0]), "r"(b[1]));
}
DEVFN void st_bf2(bf16* p, float a, float b){
    __nv_bfloat162 t = __halves2bfloat162(__float2bfloat16(a), __float2bfloat16(b));
    *reinterpret_cast<__nv_bfloat162*>(p) = t;
}

// ---------------- epilogue functors ----------------
struct EpiQ {
    bf16* q;
    DEVFN void operator()(int row, int col, float v0, float v1) const {
        int b=row>>10, n=row&1023, h=col>>6, d=col&63;
        st_bf2(q + (((long)(b*Hv+h))*Nv + n)*Dv + d, qz4(v0), qz4(v1));
    }
};
struct EpiKV {
    bf16* k; bf16* vv;
    DEVFN void operator()(int row, int col, float v0, float v1) const {
        int b=row>>10, n=row&1023;
        int rem=col&1023, h=rem>>6, d=rem&63;
        bf16* dst = ((col>>10)==0 ? k : vv) + (((long)(b*Hv+h))*Nv + n)*Dv + d;
        st_bf2(dst, qz4(v0), qz4(v1));
    }
};
struct EpiProj {
    const float* x; const float* pb; const float* aw2; const float* ab2;
    float* x1; bf16* h2;
    DEVFN void operator()(int row, int col, float v0, float v1) const {
        float a = qz4(aw2[0]), bb = qz4(ab2[0]);
        float2 xv = *(const float2*)(x + (long)row*Cv + col);
        float2 pv = *(const float2*)(pb + col);
        float y0 = v0 + qz7(pv.x),  y1 = v1 + qz7(pv.y);
        float o0 = qz4(xv.x) + qz4(y0), o1 = qz4(xv.y) + qz4(y1);
        *(float2*)(x1 + (long)row*Cv + col) = make_float2(o0, o1);
        float h0 = qz4(qz4(qz4(o0)*a) + bb);
        float h1 = qz4(qz4(qz4(o1)*a) + bb);
        st_bf2(h2 + (long)row*Cv + col, h0, h1);
    }
};
struct EpiFc1 {
    const float* b1; bf16* m;
    DEVFN void operator()(int row, int col, float v0, float v1) const {
        float2 bv = *(const float2*)(b1 + col);
        float y0 = fmaxf(v0 + qz7(bv.x), 0.f);
        float y1 = fmaxf(v1 + qz7(bv.y), 0.f);
        st_bf2(m + (long)row*HIDv + col, qz4(y0), qz4(y1));
    }
};
struct EpiFc2 {
    const float* b2; const float* x1; float* out;
    DEVFN void operator()(int row, int col, float v0, float v1) const {
        float2 bv = *(const float2*)(b2 + col);
        float2 xv = *(const float2*)(x1 + (long)row*Cv + col);
        float y0 = v0 + qz7(bv.x), y1 = v1 + qz7(bv.y);
        *(float2*)(out + (long)row*Cv + col) =
            make_float2(qz4(xv.x) + qz4(y0), qz4(xv.y) + qz4(y1));
    }
};

// ---------------- GEMM: C[128x128 tiles] = A @ B^T, BK=64, double buffered ----------------
constexpr int AROW = 144;            // 64 bf16 + 16B pad
constexpr int ASZ  = 128*AROW;       // 18432
constexpr int STG  = 2*ASZ;          // A + B stage
constexpr int GSM  = 2*STG;          // 73728 total

template<class Epi>
__global__ void __launch_bounds__(256,2)
gemm_mma(const bf16* __restrict__ A, const bf16* __restrict__ Bm, int K, Epi epi)
{
    extern __shared__ char dsm[];
    uint32_t base = s2u(dsm);
    int tid = threadIdx.x, wid = tid>>5, lane = tid&31;
    int wm = wid & 3, wn = wid >> 2;
    int m0 = blockIdx.y*128, n0 = blockIdx.x*128;
    const bf16* Ab = A + (long)m0*K;
    const bf16* Bb = Bm + (long)n0*K;
    const int KC = K >> 6;

    auto load = [&](int ch, int st){
        uint32_t ab = base + st*STG;
        uint32_t bb = ab + ASZ;
        const bf16* Ac = Ab + ch*64;
        const bf16* Bc = Bb + ch*64;
        #pragma unroll
        for(int j=0;j<4;j++){
            int i = tid + j*256; int r = i>>3, c = i&7;
            cpasync16(ab + r*AROW + c*16, Ac + (long)r*K + c*8);
            cpasync16(bb + r*AROW + c*16, Bc + (long)r*K + c*8);
        }
        cpcommit();
    };

    float acc[2][8][4];
    #pragma unroll
    for(int im=0;im<2;im++)
        #pragma unroll
        for(int j=0;j<8;j++)
            #pragma unroll
            for(int u=0;u<4;u++) acc[im][j][u]=0.f;

    load(0,0);
    int t = lane>>3, lr = lane&7;
    int rAdd = (t&1)*8 + lr, cAdd = (t>>1)*8;

    for(int c=0;c<KC;c++){
        cpwait<0>(); __syncthreads();
        if (c+1 < KC) load(c+1, (c+1)&1);
        uint32_t ab = base + (c&1)*STG, bb = ab + ASZ;
        #pragma unroll
        for(int kk=0; kk<64; kk+=16){
            uint32_t afr[2][4];
            ldsm4(afr[0], ab + (wm*32    + rAdd)*AROW + (kk + cAdd)*2);
            ldsm4(afr[1], ab + (wm*32+16 + rAdd)*AROW + (kk + cAdd)*2);
            #pragma unroll
            for(int g=0; g<4; g++){
                uint32_t r4[4];
                ldsm4(r4, bb + (wn*64 + g*16 + rAdd)*AROW + (kk + cAdd)*2);
                uint32_t b0[2]={r4[0],r4[2]}, b1[2]={r4[1],r4[3]};
                #pragma unroll
                for(int im=0;im<2;im++){
                    mma16816(acc[im][2*g],   afr[im], b0);
                    mma16816(acc[im][2*g+1], afr[im], b1);
                }
            }
        }
    }

    int row0 = m0 + wm*32 + (lane>>2);
    int col0 = n0 + wn*64 + (lane&3)*2;
    #pragma unroll
    for(int im=0;im<2;im++)
        #pragma unroll
        for(int j=0;j<8;j++){
            int r = row0 + im*16, cc = col0 + j*8;
            epi(r,   cc, acc[im][j][0], acc[im][j][1]);
            epi(r+8, cc, acc[im][j][2], acc[im][j][3]);
        }
}

// ---------------- fused attention: S=qz4(QK^T/8); p=qz7(softmax); O=p@V ----------------
// grid (8 qtiles, BH), 256 thr = 8 warps x 16 query rows. Fixed softmax max M=127/16
// (logits qz4-clipped); exp via 256-entry LUT; two passes over K (sum, then PV).
constexpr int FA_LUT = 0;
constexpr int FA_Q   = 1024;
constexpr int FA_K0  = FA_Q  + ASZ;
constexpr int FA_K1  = FA_K0 + ASZ;
constexpr int FA_V0  = FA_K1 + ASZ;
constexpr int FA_V1  = FA_V0 + ASZ;
constexpr int FA_SM  = FA_V1 + ASZ;    // 93184

__global__ void __launch_bounds__(256,1)
fattn_k(const bf16* __restrict__ q, const bf16* __restrict__ k,
        const bf16* __restrict__ v, bf16* __restrict__ z2)
{
    extern __shared__ char dsm[];
    float* lut = (float*)dsm;
    uint32_t base = s2u(dsm);
    uint32_t qs = base + FA_Q;
    uint32_t ks[2] = {base+FA_K0, base+FA_K1};
    uint32_t vs[2] = {base+FA_V0, base+FA_V1};

    int tid = threadIdx.x, wid = tid>>5, lane = tid&31;
    int bh = blockIdx.y, b = bh>>4, h = bh&15;
    int q0 = blockIdx.x*128;
    const bf16* Qb = q + ((long)bh*Nv + q0)*Dv;
    const bf16* Kb = k + (long)bh*Nv*Dv;
    const bf16* Vb = v + (long)bh*Nv*Dv;

    lut[tid] = expf((float)(tid-128)*0.0625f - 7.9375f);   // exp(logit - M)

    #pragma unroll
    for(int j=0;j<4;j++){
        int i = tid + j*256; int r = i>>3, c = i&7;
        cpasync16(qs + r*AROW + c*16, Qb + (long)r*Dv + c*8);
    }
    cpcommit();

    int t = lane>>3, lr = lane&7;
    int rAdd = (t&1)*8 + lr, cAdd = (t>>1)*8;

    auto loadK = [&](int c, int st){
        const bf16* src = Kb + (long)(c*128)*Dv;
        #pragma unroll
        for(int j=0;j<4;j++){
            int i = tid + j*256; int r = i>>3, cc = i&7;
            cpasync16(ks[st] + r*AROW + cc*16, src + (long)r*Dv + cc*8);
        }
        cpcommit();
    };
    auto loadKV = [&](int c, int st){
        const bf16* sk = Kb + (long)(c*128)*Dv;
        const bf16* sv = Vb + (long)(c*128)*Dv;
        #pragma unroll
        for(int j=0;j<4;j++){
            int i = tid + j*256; int r = i>>3, cc = i&7;
            cpasync16(ks[st] + r*AROW + cc*16, sk + (long)r*Dv + cc*8);
            cpasync16(vs[st] + r*AROW + cc*16, sv + (long)r*Dv + cc*8);
        }
        cpcommit();
    };

    loadK(0, 0);
    cpwait<0>(); __syncthreads();                 // Q + K0 + LUT ready

    uint32_t qf[4][4];
    #pragma unroll
    for(int kk=0;kk<4;kk++)
        ldsm4(qf[kk], qs + (wid*16 + rAdd)*AROW + (kk*16 + cAdd)*2);

    float sacc[16][4];
    auto computeS = [&](uint32_t kb_){
        #pragma unroll
        for(int g=0;g<16;g++){ sacc[g][0]=0.f; sacc[g][1]=0.f; sacc[g][2]=0.f; sacc[g][3]=0.f; }
        #pragma unroll
        for(int kk=0;kk<4;kk++){
            #pragma unroll
            for(int kg=0;kg<8;kg++){
                uint32_t r4[4];
                ldsm4(r4, kb_ + (kg*16 + rAdd)*AROW + (kk*16 + cAdd)*2);
                uint32_t b0[2]={r4[0],r4[2]}, b1[2]={r4[1],r4[3]};
                mma16816(sacc[2*kg],   qf[kk], b0);
                mma16816(sacc[2*kg+1], qf[kk], b1);
            }
        }
    };
    auto lutv = [&](float s)->float{
        float r = rintf(s*2.0f);                  // qz4(s*0.125) index: s*0.125*16
        r = fminf(fmaxf(r,-128.f),127.f);
        return lut[(int)r + 128];
    };

    // ---- pass A: row sums of exp(logit - M) ----
    float rs0 = 0.f, rs1 = 0.f;
    for(int c=0;c<8;c++){
        cpwait<0>(); __syncthreads();
        if (c<7) loadK(c+1, (c+1)&1);
        computeS(ks[c&1]);
        #pragma unroll
        for(int g=0;g<16;g++){
            rs0 += lutv(sacc[g][0]) + lutv(sacc[g][1]);
            rs1 += lutv(sacc[g][2]) + lutv(sacc[g][3]);
        }
    }
    rs0 += __shfl_xor_sync(0xffffffffu, rs0, 1);
    rs0 += __shfl_xor_sync(0xffffffffu, rs0, 2);
    rs1 += __shfl_xor_sync(0xffffffffu, rs1, 1);
    rs1 += __shfl_xor_sync(0xffffffffu, rs1, 2);
    float inv0 = 1.0f/rs0, inv1 = 1.0f/rs1;

    auto pq = [&](float s, float inv)->uint32_t{  // qz7(p) as bf16 bits
        float p = lutv(s)*inv;
        float r = rintf(p*128.f);
        r = fminf(fmaxf(r,-128.f),127.f);
        bf16 bv = __float2bfloat16(r*0.0078125f);
        return (uint32_t)*reinterpret_cast<uint16_t*>(&bv);
    };

    // ---- pass B: recompute S, quantize P, O += P @ V ----
    float oacc[8][4];
    #pragma unroll
    for(int j=0;j<8;j++){ oacc[j][0]=0.f; oacc[j][1]=0.f; oacc[j][2]=0.f; oacc[j][3]=0.f; }

    loadKV(0, 0);
    for(int c=0;c<8;c++){
        cpwait<0>(); __syncthreads();
        if (c<7) loadKV(c+1, (c+1)&1);
        computeS(ks[c&1]);
        #pragma unroll
        for(int kk8=0;kk8<8;kk8++){
            int g0 = 2*kk8, g1 = g0+1;
            uint32_t pa[4];
            pa[0] = pq(sacc[g0][0],inv0) | (pq(sacc[g0][1],inv0)<<16);
            pa[1] = pq(sacc[g0][2],inv1) | (pq(sacc[g0][3],inv1)<<16);
            pa[2] = pq(sacc[g1][0],inv0) | (pq(sacc[g1][1],inv0)<<16);
            pa[3] = pq(sacc[g1][2],inv1) | (pq(sacc[g1][3],inv1)<<16);
            #pragma unroll
            for(int dg=0;dg<4;dg++){
                uint32_t r4[4];
                ldsm4t(r4, vs[c&1] + (kk8*16 + rAdd)*AROW + (dg*16 + cAdd)*2);
                uint32_t b0[2]={r4[0],r4[1]}, b1[2]={r4[2],r4[3]};
                mma16816(oacc[2*dg],   pa, b0);
                mma16816(oacc[2*dg+1], pa, b1);
            }
        }
    }

    // ---- epilogue: z2[b, n, h*64+d] = qz4(o) ----
    int n = q0 + wid*16 + (lane>>2);
    long ro = ((long)(b*Nv) + n)*Cv + h*Dv;
    int d0 = 2*(lane&3);
    #pragma unroll
    for(int og=0;og<8;og++){
        st_bf2(z2 + ro +        og*8 + d0, qz4(oacc[og][0]), qz4(oacc[og][1]));
        st_bf2(z2 + ro + 8*Cv + og*8 + d0, qz4(oacc[og][2]), qz4(oacc[og][3]));
    }
}

// ---------------- elementwise kernels ----------------
__global__ void quantw4_k(const float4* __restrict__ src, uint2* __restrict__ dst, int n4){
    int i = blockIdx.x*blockDim.x + threadIdx.x;
    if(i<n4){
        float4 v = src[i];
        __nv_bfloat162 lo = __halves2bfloat162(__float2bfloat16(qz7(v.x)), __float2bfloat16(qz7(v.y)));
        __nv_bfloat162 hi = __halves2bfloat162(__float2bfloat16(qz7(v.z)), __float2bfloat16(qz7(v.w)));
        dst[i] = make_uint2(*(uint32_t*)&lo, *(uint32_t*)&hi);
    }
}
__global__ void affine4_k(const float4* __restrict__ x, const float* __restrict__ aw,
                          const float* __restrict__ ab, uint2* __restrict__ out, int n4){
    int i = blockIdx.x*blockDim.x + threadIdx.x;
    if(i<n4){
        float a = qz4(aw[0]), b = qz4(ab[0]);
        float4 v = x[i];
        float o[4] = {v.x,v.y,v.z,v.w};
        #pragma unroll
        for(int u=0;u<4;u++){ float t = qz4(o[u])*a; o[u] = qz4(qz4(t)+b); }
        __nv_bfloat162 lo = __halves2bfloat162(__float2bfloat16(o[0]), __float2bfloat16(o[1]));
        __nv_bfloat162 hi = __halves2bfloat162(__float2bfloat16(o[2]), __float2bfloat16(o[3]));
        out[i] = make_uint2(*(uint32_t*)&lo, *(uint32_t*)&hi);
    }
}

// ---------------- host launcher ----------------
extern "C" void kernel_launch(void* const* d_in, const int* in_sizes, int n_in,
                              void* d_out, int out_size)
{
    (void)in_sizes; (void)n_in; (void)out_size;
    const float* x   = (const float*)d_in[0];
    const float* qw  = (const float*)d_in[1];
    const float* kvw = (const float*)d_in[2];
    const float* pw  = (const float*)d_in[3];
    const float* pb  = (const float*)d_in[4];
    const float* f1w = (const float*)d_in[5];
    const float* f1b = (const float*)d_in[6];
    const float* f2w = (const float*)d_in[7];
    const float* f2b = (const float*)d_in[8];
    const float* a1w = (const float*)d_in[9];
    const float* a1b = (const float*)d_in[10];
    const float* a2w = (const float*)d_in[11];
    const float* a2b = (const float*)d_in[12];
    float* out = (float*)d_out;

    bf16 *wq,*wkv,*wpr,*wf1,*wf2,*h1,*qb,*kb,*vb,*z2,*h2,*m;
    float *x1;
    cudaGetSymbolAddress((void**)&wq,  g_wq);
    cudaGetSymbolAddress((void**)&wkv, g_wkv);
    cudaGetSymbolAddress((void**)&wpr, g_wpr);
    cudaGetSymbolAddress((void**)&wf1, g_wf1);
    cudaGetSymbolAddress((void**)&wf2, g_wf2);
    cudaGetSymbolAddress((void**)&h1,  g_h1);
    cudaGetSymbolAddress((void**)&qb,  g_qb);
    cudaGetSymbolAddress((void**)&kb,  g_kb);
    cudaGetSymbolAddress((void**)&vb,  g_vb);
    cudaGetSymbolAddress((void**)&z2,  g_z2);
    cudaGetSymbolAddress((void**)&x1,  g_x1);
    cudaGetSymbolAddress((void**)&h2,  g_h2);
    cudaGetSymbolAddress((void**)&m,   g_m);

    cudaFuncSetAttribute(gemm_mma<EpiQ  >, cudaFuncAttributeMaxDynamicSharedMemorySize, GSM);
    cudaFuncSetAttribute(gemm_mma<EpiKV >, cudaFuncAttributeMaxDynamicSharedMemorySize, GSM);
    cudaFuncSetAttribute(gemm_mma<EpiProj>,cudaFuncAttributeMaxDynamicSharedMemorySize, GSM);
    cudaFuncSetAttribute(gemm_mma<EpiFc1>, cudaFuncAttributeMaxDynamicSharedMemorySize, GSM);
    cudaFuncSetAttribute(gemm_mma<EpiFc2>, cudaFuncAttributeMaxDynamicSharedMemorySize, GSM);
    cudaFuncSetAttribute(fattn_k,          cudaFuncAttributeMaxDynamicSharedMemorySize, FA_SM);

    // 1) quantize weights
    quantw4_k<<<(Cv*Cv/4+255)/256,   256>>>((const float4*)qw,  (uint2*)wq,  Cv*Cv/4);
    quantw4_k<<<(2*Cv*Cv/4+255)/256, 256>>>((const float4*)kvw, (uint2*)wkv, 2*Cv*Cv/4);
    quantw4_k<<<(Cv*Cv/4+255)/256,   256>>>((const float4*)pw,  (uint2*)wpr, Cv*Cv/4);
    quantw4_k<<<(HIDv*Cv/4+255)/256, 256>>>((const float4*)f1w, (uint2*)wf1, HIDv*Cv/4);
    quantw4_k<<<(Cv*HIDv/4+255)/256, 256>>>((const float4*)f2w, (uint2*)wf2, Cv*HIDv/4);

    // 2) affine1 + input quant
    affine4_k<<<(Tv*Cv/4+255)/256, 256>>>((const float4*)x, a1w, a1b, (uint2*)h1, Tv*Cv/4);

    // 3) q / kv projections
    { EpiQ  e{qb};
      gemm_mma<EpiQ ><<<dim3(Cv/128,  Tv/128), 256, GSM>>>(h1, wq,  Cv, e); }
    { EpiKV e{kb,vb};
      gemm_mma<EpiKV><<<dim3(2*Cv/128,Tv/128), 256, GSM>>>(h1, wkv, Cv, e); }

    // 4) fused attention -> z2
    fattn_k<<<dim3(Nv/128, BH), 256, FA_SM>>>(qb, kb, vb, z2);

    // 5) proj + add1 + affine2
    { EpiProj e{x, pb, a2w, a2b, x1, h2};
      gemm_mma<EpiProj><<<dim3(Cv/128,  Tv/128), 256, GSM>>>(z2, wpr, Cv, e); }
    // 6) fc1 + relu
    { EpiFc1 e{f1b, m};
      gemm_mma<EpiFc1><<<dim3(HIDv/128, Tv/128), 256, GSM>>>(h2, wf1, Cv, e); }
    // 7) fc2 + add2 -> out
    { EpiFc2 e{f2b, x1, out};
      gemm_mma<EpiFc2><<<dim3(Cv/128,  Tv/128), 256, GSM>>>(m, wf2, HIDv, e); }
}

// round 6
// speedup vs baseline: 2.0598x; 1.1415x over previous
#include <cuda_runtime.h>
#include <cuda_bf16.h>
#include <cstdint>

typedef __nv_bfloat16 bf16;
#define DEVFN __device__ __forceinline__

// toolchain targets sm_103 (no 'a') -> tcgen05 unavailable; mma.sync + cp.async path.

// ---------------- problem dims ----------------
#define Bv   4
#define Nv   1024
#define Cv   1024
#define Hv   16
#define Dv   64
#define HIDv 4096
#define Tv   (Bv*Nv)
#define BH   (Bv*Hv)

// ---------------- quantizers ----------------
DEVFN float qz4(float x){ float r = rintf(x*16.0f);  r = fminf(fmaxf(r,-128.0f),127.0f); return r*0.0625f; }
DEVFN float qz7(float x){ float r = rintf(x*128.0f); r = fminf(fmaxf(r,-128.0f),127.0f); return r*0.0078125f; }

// ---------------- device scratch ----------------
__device__ __align__(128) bf16 g_wqkv[3*Cv*Cv];      // [q | k | v] rows
__device__ __align__(128) bf16 g_wpr [Cv*Cv];
__device__ __align__(128) bf16 g_wf1 [HIDv*Cv];
__device__ __align__(128) bf16 g_wf2 [Cv*HIDv];
__device__ __align__(128) bf16 g_h1  [Tv*Cv];
__device__ __align__(128) bf16 g_qb  [BH*Nv*Dv];
__device__ __align__(128) bf16 g_kb  [BH*Nv*Dv];
__device__ __align__(128) bf16 g_vb  [BH*Nv*Dv];
__device__ __align__(128) bf16 g_z2  [Tv*Cv];
__device__ __align__(128) float g_x1 [Tv*Cv];
__device__ __align__(128) bf16 g_h2  [Tv*Cv];
__device__ __align__(128) bf16 g_m   [Tv*HIDv];

// ---------------- PTX helpers ----------------
DEVFN uint32_t s2u(const void* p){
    uint32_t a;
    asm("{ .reg .u64 t; cvta.to.shared.u64 t, %1; cvt.u32.u64 %0, t; }" : "=r"(a) : "l"(p));
    return a;
}
DEVFN void cpasync16(uint32_t d, const void* s){
    asm volatile("cp.async.cg.shared.global [%0], [%1], 16;" :: "r"(d), "l"(s));
}
DEVFN void cpcommit(){ asm volatile("cp.async.commit_group;" ::: "memory"); }
template<int N> DEVFN void cpwait(){ asm volatile("cp.async.wait_group %0;" :: "n"(N) : "memory"); }

DEVFN void ldsm4(uint32_t* r, uint32_t addr){
    asm volatile("ldmatrix.sync.aligned.m8n8.x4.shared.b16 {%0,%1,%2,%3}, [%4];"
        : "=r"(r[0]), "=r"(r[1]), "=r"(r[2]), "=r"(r[3]) : "r"(addr));
}
DEVFN void ldsm4t(uint32_t* r, uint32_t addr){
    asm volatile("ldmatrix.sync.aligned.m8n8.x4.trans.shared.b16 {%0,%1,%2,%3}, [%4];"
        : "=r"(r[0]), "=r"(r[1]), "=r"(r[2]), "=r"(r[3]) : "r"(addr));
}
DEVFN void mma16816(float* c, const uint32_t* a, const uint32_t* b){
    asm volatile("mma.sync.aligned.m16n8k16.row.col.f32.bf16.bf16.f32 "
        "{%0,%1,%2,%3}, {%4,%5,%6,%7}, {%8,%9}, {%0,%1,%2,%3};"
        : "+f"(c[0]), "+f"(c[1]), "+f"(c[2]), "+f"(c[3])
        : "r"(a[0]), "r"(a[1]), "r"(a[2]), "r"(a[3]), "r"(b[0]), "r"(b[1]));
}
DEVFN void st_bf2(bf16* p, float a, float b){
    __nv_bfloat162 t = __halves2bfloat162(__float2bfloat16(a), __float2bfloat16(b));
    *reinterpret_cast<__nv_bfloat162*>(p) = t;
}
// swizzled smem offset: tile rows are 128B; c16 = 16B chunk index (0..7)
DEVFN uint32_t swz(uint32_t r, uint32_t c16){ return (r<<7) + (((c16 ^ (r&7)))<<4); }

// ---------------- epilogue functors ----------------
struct EpiQKV {
    bf16* q; bf16* k; bf16* v;
    DEVFN void operator()(int row, int col, float v0, float v1) const {
        int b=row>>10, n=row&1023;
        int sel=col>>10, rem=col&1023, h=rem>>6, d=rem&63;
        bf16* dst = (sel==0 ? q : (sel==1 ? k : v)) + (((long)(b*Hv+h))*Nv + n)*Dv + d;
        st_bf2(dst, qz4(v0), qz4(v1));
    }
};
struct EpiProj {
    const float* x; const float* pb; const float* aw2; const float* ab2;
    float* x1; bf16* h2;
    DEVFN void operator()(int row, int col, float v0, float v1) const {
        float a = qz4(aw2[0]), bb = qz4(ab2[0]);
        float2 xv = *(const float2*)(x + (long)row*Cv + col);
        float2 pv = *(const float2*)(pb + col);
        float y0 = v0 + qz7(pv.x),  y1 = v1 + qz7(pv.y);
        float o0 = qz4(xv.x) + qz4(y0), o1 = qz4(xv.y) + qz4(y1);
        *(float2*)(x1 + (long)row*Cv + col) = make_float2(o0, o1);
        float h0 = qz4(qz4(qz4(o0)*a) + bb);
        float h1 = qz4(qz4(qz4(o1)*a) + bb);
        st_bf2(h2 + (long)row*Cv + col, h0, h1);
    }
};
struct EpiFc1 {
    const float* b1; bf16* m;
    DEVFN void operator()(int row, int col, float v0, float v1) const {
        float2 bv = *(const float2*)(b1 + col);
        float y0 = fmaxf(v0 + qz7(bv.x), 0.f);
        float y1 = fmaxf(v1 + qz7(bv.y), 0.f);
        st_bf2(m + (long)row*HIDv + col, qz4(y0), qz4(y1));
    }
};
struct EpiFc2 {
    const float* b2; const float* x1; float* out;
    DEVFN void operator()(int row, int col, float v0, float v1) const {
        float2 bv = *(const float2*)(b2 + col);
        float2 xv = *(const float2*)(x1 + (long)row*Cv + col);
        float y0 = v0 + qz7(bv.x), y1 = v1 + qz7(bv.y);
        *(float2*)(out + (long)row*Cv + col) =
            make_float2(qz4(xv.x) + qz4(y0), qz4(xv.y) + qz4(y1));
    }
};

// ---------------- GEMM: C[128x128] = A @ B^T, BK=64, 3-stage, swizzled ----------------
constexpr int TILE = 128*128;        // 16 KB (128 rows x 128 B)
constexpr int GSTG = 2*TILE;         // A + B stage = 32 KB
constexpr int GSM  = 3*GSTG;         // 96 KB

template<class Epi>
__global__ void __launch_bounds__(256,2)
gemm_mma(const bf16* __restrict__ A, const bf16* __restrict__ Bm, int K, Epi epi)
{
    extern __shared__ char dsm[];
    uint32_t base = s2u(dsm);
    int tid = threadIdx.x, wid = tid>>5, lane = tid&31;
    int wm = wid & 3, wn = wid >> 2;
    int m0 = blockIdx.y*128, n0 = blockIdx.x*128;
    const bf16* Ab = A + (long)m0*K;
    const bf16* Bb = Bm + (long)n0*K;
    const int KC = K >> 6;

    auto load = [&](int ch, int st){
        uint32_t ab = base + st*GSTG, bb = ab + TILE;
        const bf16* Ac = Ab + ch*64;
        const bf16* Bc = Bb + ch*64;
        #pragma unroll
        for(int j=0;j<4;j++){
            int i = tid + j*256; int r = i>>3, c = i&7;
            cpasync16(ab + swz(r,c), Ac + (long)r*K + c*8);
            cpasync16(bb + swz(r,c), Bc + (long)r*K + c*8);
        }
        cpcommit();
    };

    float acc[2][8][4];
    #pragma unroll
    for(int im=0;im<2;im++)
        #pragma unroll
        for(int j=0;j<8;j++)
            #pragma unroll
            for(int u=0;u<4;u++) acc[im][j][u]=0.f;

    load(0,0);
    load(1,1);
    int t = lane>>3, lr = lane&7;
    int rAdd = (t&1)*8 + lr, cAdd = (t>>1)*8;

    for(int c=0;c<KC;c++){
        if (c+1 < KC) cpwait<1>(); else cpwait<0>();
        __syncthreads();
        if (c+2 < KC) load(c+2, (c+2)%3);
        uint32_t ab = base + (c%3)*GSTG, bb = ab + TILE;
        #pragma unroll
        for(int kk=0; kk<64; kk+=16){
            int ch = (kk + cAdd)>>3;
            uint32_t afr[2][4];
            #pragma unroll
            for(int im=0;im<2;im++){
                int row = wm*32 + im*16 + rAdd;
                ldsm4(afr[im], ab + (row<<7) + (((ch ^ (row&7)))<<4));
            }
            #pragma unroll
            for(int g=0; g<4; g++){
                int row = wn*64 + g*16 + rAdd;
                uint32_t r4[4];
                ldsm4(r4, bb + (row<<7) + (((ch ^ (row&7)))<<4));
                uint32_t b0[2]={r4[0],r4[2]}, b1[2]={r4[1],r4[3]};
                #pragma unroll
                for(int im=0;im<2;im++){
                    mma16816(acc[im][2*g],   afr[im], b0);
                    mma16816(acc[im][2*g+1], afr[im], b1);
                }
            }
        }
    }

    int row0 = m0 + wm*32 + (lane>>2);
    int col0 = n0 + wn*64 + (lane&3)*2;
    #pragma unroll
    for(int im=0;im<2;im++)
        #pragma unroll
        for(int j=0;j<8;j++){
            int r = row0 + im*16, cc = col0 + j*8;
            epi(r,   cc, acc[im][j][0], acc[im][j][1]);
            epi(r+8, cc, acc[im][j][2], acc[im][j][3]);
        }
}

// ---------------- fused attention ----------------
// S=qz4(QK^T/8), p=qz7(exp(S-M)/sum) with fixed M=127/16 (logits qz4-clipped),
// exp via 256-entry LUT, two passes over keys. Per-key-group structure keeps
// live registers ~60 -> 2 CTAs/SM.
constexpr int FA_Q  = 1024;                 // after 256-float LUT
constexpr int FA_K0 = FA_Q  + TILE;
constexpr int FA_K1 = FA_K0 + TILE;
constexpr int FA_V0 = FA_K1 + TILE;
constexpr int FA_V1 = FA_V0 + TILE;
constexpr int FA_SM = FA_V1 + TILE;         // 82944

__global__ void __launch_bounds__(256,2)
fattn_k(const bf16* __restrict__ q, const bf16* __restrict__ k,
        const bf16* __restrict__ v, bf16* __restrict__ z2)
{
    extern __shared__ char dsm[];
    float* lut = (float*)dsm;
    uint32_t base = s2u(dsm);
    uint32_t qs = base + FA_Q;
    uint32_t ks[2] = {base+FA_K0, base+FA_K1};
    uint32_t vs[2] = {base+FA_V0, base+FA_V1};

    int tid = threadIdx.x, wid = tid>>5, lane = tid&31;
    int bh = blockIdx.y, b = bh>>4, h = bh&15;
    int q0 = blockIdx.x*128;
    const bf16* Qb = q + ((long)bh*Nv + q0)*Dv;
    const bf16* Kb = k + (long)bh*Nv*Dv;
    const bf16* Vb = v + (long)bh*Nv*Dv;

    lut[tid] = expf((float)(tid-128)*0.0625f - 7.9375f);

    #pragma unroll
    for(int j=0;j<4;j++){
        int i = tid + j*256; int r = i>>3, c = i&7;
        cpasync16(qs + swz(r,c), Qb + (long)r*Dv + c*8);
    }
    cpcommit();

    int t = lane>>3, lr = lane&7;
    int rAdd = (t&1)*8 + lr, cAdd = (t>>1)*8;

    auto loadK = [&](int c, int st){
        const bf16* src = Kb + (long)(c*128)*Dv;
        #pragma unroll
        for(int j=0;j<4;j++){
            int i = tid + j*256; int r = i>>3, cc = i&7;
            cpasync16(ks[st] + swz(r,cc), src + (long)r*Dv + cc*8);
        }
        cpcommit();
    };
    auto loadKV = [&](int c, int st){
        const bf16* sk = Kb + (long)(c*128)*Dv;
        const bf16* sv = Vb + (long)(c*128)*Dv;
        #pragma unroll
        for(int j=0;j<4;j++){
            int i = tid + j*256; int r = i>>3, cc = i&7;
            cpasync16(ks[st] + swz(r,cc), sk + (long)r*Dv + cc*8);
            cpasync16(vs[st] + swz(r,cc), sv + (long)r*Dv + cc*8);
        }
        cpcommit();
    };

    loadK(0, 0);
    cpwait<0>(); __syncthreads();

    uint32_t qf[4][4];
    #pragma unroll
    for(int kk=0;kk<4;kk++){
        int row = wid*16 + rAdd;
        int ch = (kk*16 + cAdd)>>3;
        ldsm4(qf[kk], qs + (row<<7) + (((ch ^ (row&7)))<<4));
    }

    // compute S for one 16-key group: s2[0]=keys kg*16+0..7, s2[1]=+8..15
    auto computeS2 = [&](uint32_t kb_, int kg, float s2[2][4]){
        #pragma unroll
        for(int u=0;u<4;u++){ s2[0][u]=0.f; s2[1][u]=0.f; }
        #pragma unroll
        for(int kk=0;kk<4;kk++){
            int row = kg*16 + rAdd;
            int ch = (kk*16 + cAdd)>>3;
            uint32_t r4[4];
            ldsm4(r4, kb_ + (row<<7) + (((ch ^ (row&7)))<<4));
            uint32_t b0[2]={r4[0],r4[2]}, b1[2]={r4[1],r4[3]};
            mma16816(s2[0], qf[kk], b0);
            mma16816(s2[1], qf[kk], b1);
        }
    };
    auto lutv = [&](float s)->float{
        float r = rintf(s*2.0f);
        r = fminf(fmaxf(r,-128.f),127.f);
        return lut[(int)r + 128];
    };

    // ---- pass A: row sums ----
    float rs0 = 0.f, rs1 = 0.f;
    for(int c=0;c<8;c++){
        cpwait<0>(); __syncthreads();
        if (c<7) loadK(c+1, (c+1)&1);
        #pragma unroll
        for(int kg=0;kg<8;kg++){
            float s2[2][4];
            computeS2(ks[c&1], kg, s2);
            rs0 += lutv(s2[0][0]) + lutv(s2[0][1]) + lutv(s2[1][0]) + lutv(s2[1][1]);
            rs1 += lutv(s2[0][2]) + lutv(s2[0][3]) + lutv(s2[1][2]) + lutv(s2[1][3]);
        }
    }
    rs0 += __shfl_xor_sync(0xffffffffu, rs0, 1);
    rs0 += __shfl_xor_sync(0xffffffffu, rs0, 2);
    rs1 += __shfl_xor_sync(0xffffffffu, rs1, 1);
    rs1 += __shfl_xor_sync(0xffffffffu, rs1, 2);
    float inv0 = 1.0f/rs0, inv1 = 1.0f/rs1;

    auto pq = [&](float s, float inv)->uint32_t{
        float p = lutv(s)*inv;
        float r = rintf(p*128.f);
        r = fminf(fmaxf(r,-128.f),127.f);
        bf16 bv = __float2bfloat16(r*0.0078125f);
        return (uint32_t)*reinterpret_cast<uint16_t*>(&bv);
    };

    // ---- pass B: recompute S per key group, O += P @ V ----
    float oacc[8][4];
    #pragma unroll
    for(int j=0;j<8;j++){ oacc[j][0]=0.f; oacc[j][1]=0.f; oacc[j][2]=0.f; oacc[j][3]=0.f; }

    loadKV(0, 0);
    for(int c=0;c<8;c++){
        cpwait<0>(); __syncthreads();
        if (c<7) loadKV(c+1, (c+1)&1);
        #pragma unroll
        for(int kg=0;kg<8;kg++){
            float s2[2][4];
            computeS2(ks[c&1], kg, s2);
            uint32_t pa[4];
            pa[0] = pq(s2[0][0],inv0) | (pq(s2[0][1],inv0)<<16);
            pa[1] = pq(s2[0][2],inv1) | (pq(s2[0][3],inv1)<<16);
            pa[2] = pq(s2[1][0],inv0) | (pq(s2[1][1],inv0)<<16);
            pa[3] = pq(s2[1][2],inv1) | (pq(s2[1][3],inv1)<<16);
            #pragma unroll
            for(int dg=0;dg<4;dg++){
                int row = kg*16 + rAdd;
                int ch = (dg*16 + cAdd)>>3;
                uint32_t r4[4];
                ldsm4t(r4, vs[c&1] + (row<<7) + (((ch ^ (row&7)))<<4));
                uint32_t b0[2]={r4[0],r4[1]}, b1[2]={r4[2],r4[3]};
                mma16816(oacc[2*dg],   pa, b0);
                mma16816(oacc[2*dg+1], pa, b1);
            }
        }
    }

    int n = q0 + wid*16 + (lane>>2);
    long ro = ((long)(b*Nv) + n)*Cv + h*Dv;
    int d0 = 2*(lane&3);
    #pragma unroll
    for(int og=0;og<8;og++){
        st_bf2(z2 + ro +        og*8 + d0, qz4(oacc[og][0]), qz4(oacc[og][1]));
        st_bf2(z2 + ro + 8*Cv + og*8 + d0, qz4(oacc[og][2]), qz4(oacc[og][3]));
    }
}

// ---------------- elementwise kernels ----------------
// fused weight quantization: 12288 blocks cover wq|wkv(->wqkv), wpr, wf1, wf2
__global__ void quantw_all(const float4* qw, const float4* kvw, const float4* pw,
                           const float4* f1w, const float4* f2w,
                           uint2* wqkv, uint2* wpr, uint2* wf1, uint2* wf2)
{
    int bx = blockIdx.x;
    const float4* src; uint2* dst; int li;
    if      (bx < 1024){ src=qw;  dst=wqkv;                li=bx; }
    else if (bx < 3072){ src=kvw; dst=wqkv + 262144;       li=bx-1024; }
    else if (bx < 4096){ src=pw;  dst=wpr;                 li=bx-3072; }
    else if (bx < 8192){ src=f1w; dst=wf1;                 li=bx-4096; }
    else               { src=f2w; dst=wf2;                 li=bx-8192; }
    int i = li*256 + threadIdx.x;
    float4 v = src[i];
    __nv_bfloat162 lo = __halves2bfloat162(__float2bfloat16(qz7(v.x)), __float2bfloat16(qz7(v.y)));
    __nv_bfloat162 hi = __halves2bfloat162(__float2bfloat16(qz7(v.z)), __float2bfloat16(qz7(v.w)));
    dst[i] = make_uint2(*(uint32_t*)&lo, *(uint32_t*)&hi);
}
__global__ void affine4_k(const float4* __restrict__ x, const float* __restrict__ aw,
                          const float* __restrict__ ab, uint2* __restrict__ out, int n4){
    int i = blockIdx.x*blockDim.x + threadIdx.x;
    if(i<n4){
        float a = qz4(aw[0]), b = qz4(ab[0]);
        float4 v = x[i];
        float o[4] = {v.x,v.y,v.z,v.w};
        #pragma unroll
        for(int u=0;u<4;u++){ float t = qz4(o[u])*a; o[u] = qz4(qz4(t)+b); }
        __nv_bfloat162 lo = __halves2bfloat162(__float2bfloat16(o[0]), __float2bfloat16(o[1]));
        __nv_bfloat162 hi = __halves2bfloat162(__float2bfloat16(o[2]), __float2bfloat16(o[3]));
        out[i] = make_uint2(*(uint32_t*)&lo, *(uint32_t*)&hi);
    }
}

// ---------------- host launcher ----------------
extern "C" void kernel_launch(void* const* d_in, const int* in_sizes, int n_in,
                              void* d_out, int out_size)
{
    (void)in_sizes; (void)n_in; (void)out_size;
    const float* x   = (const float*)d_in[0];
    const float* qw  = (const float*)d_in[1];
    const float* kvw = (const float*)d_in[2];
    const float* pw  = (const float*)d_in[3];
    const float* pb  = (const float*)d_in[4];
    const float* f1w = (const float*)d_in[5];
    const float* f1b = (const float*)d_in[6];
    const float* f2w = (const float*)d_in[7];
    const float* f2b = (const float*)d_in[8];
    const float* a1w = (const float*)d_in[9];
    const float* a1b = (const float*)d_in[10];
    const float* a2w = (const float*)d_in[11];
    const float* a2b = (const float*)d_in[12];
    float* out = (float*)d_out;

    bf16 *wqkv,*wpr,*wf1,*wf2,*h1,*qb,*kb,*vb,*z2,*h2,*m;
    float *x1;
    cudaGetSymbolAddress((void**)&wqkv,g_wqkv);
    cudaGetSymbolAddress((void**)&wpr, g_wpr);
    cudaGetSymbolAddress((void**)&wf1, g_wf1);
    cudaGetSymbolAddress((void**)&wf2, g_wf2);
    cudaGetSymbolAddress((void**)&h1,  g_h1);
    cudaGetSymbolAddress((void**)&qb,  g_qb);
    cudaGetSymbolAddress((void**)&kb,  g_kb);
    cudaGetSymbolAddress((void**)&vb,  g_vb);
    cudaGetSymbolAddress((void**)&z2,  g_z2);
    cudaGetSymbolAddress((void**)&x1,  g_x1);
    cudaGetSymbolAddress((void**)&h2,  g_h2);
    cudaGetSymbolAddress((void**)&m,   g_m);

    cudaFuncSetAttribute(gemm_mma<EpiQKV>, cudaFuncAttributeMaxDynamicSharedMemorySize, GSM);
    cudaFuncSetAttribute(gemm_mma<EpiProj>,cudaFuncAttributeMaxDynamicSharedMemorySize, GSM);
    cudaFuncSetAttribute(gemm_mma<EpiFc1>, cudaFuncAttributeMaxDynamicSharedMemorySize, GSM);
    cudaFuncSetAttribute(gemm_mma<EpiFc2>, cudaFuncAttributeMaxDynamicSharedMemorySize, GSM);
    cudaFuncSetAttribute(fattn_k,          cudaFuncAttributeMaxDynamicSharedMemorySize, FA_SM);

    // 1) quantize all weights (one launch)
    quantw_all<<<12288, 256>>>((const float4*)qw, (const float4*)kvw, (const float4*)pw,
                               (const float4*)f1w, (const float4*)f2w,
                               (uint2*)wqkv, (uint2*)wpr, (uint2*)wf1, (uint2*)wf2);

    // 2) affine1 + input quant
    affine4_k<<<(Tv*Cv/4+255)/256, 256>>>((const float4*)x, a1w, a1b, (uint2*)h1, Tv*Cv/4);

    // 3) fused qkv projection
    { EpiQKV e{qb,kb,vb};
      gemm_mma<EpiQKV><<<dim3(3*Cv/128, Tv/128), 256, GSM>>>(h1, wqkv, Cv, e); }

    // 4) fused attention -> z2
    fattn_k<<<dim3(Nv/128, BH), 256, FA_SM>>>(qb, kb, vb, z2);

    // 5) proj + add1 + affine2
    { EpiProj e{x, pb, a2w, a2b, x1, h2};
      gemm_mma<EpiProj><<<dim3(Cv/128,  Tv/128), 256, GSM>>>(z2, wpr, Cv, e); }
    // 6) fc1 + relu
    { EpiFc1 e{f1b, m};
      gemm_mma<EpiFc1><<<dim3(HIDv/128, Tv/128), 256, GSM>>>(h2, wf1, Cv, e); }
    // 7) fc2 + add2 -> out
    { EpiFc2 e{f2b, x1, out};
      gemm_mma<EpiFc2><<<dim3(Cv/128,  Tv/128), 256, GSM>>>(m, wf2, HIDv, e); }
}